// round 13
// baseline (speedup 1.0000x reference)
#include <cuda_runtime.h>
#include <cuda_fp16.h>
#include <cstdint>

// ---------------------------------------------------------------------------
// Problem constants
// ---------------------------------------------------------------------------
#define M_ 4096
#define N_ 12288
#define K_ 4096
#define NW_ (N_ / 8)          // packed int32 words per k-row = 1536

// ---------------------------------------------------------------------------
// GEMM tiling: CTA 128x192x64, 8 warps (2x4), warp tile 64x48, mma.m16n8k16
// Grid 32x64 = 2048 CTAs -> 13.84 waves (tail loss 1.2% vs 6.0% at BN=256)
// ---------------------------------------------------------------------------
#define BM 128
#define BN 192
#define BK 64
#define STAGES 3
#define KTILES (K_ / BK)        // 64
#define THREADS 256

// SMEM layout per stage (fp16):
//  A: [128 rows][64 halves + 8 pad]  pitch 144B (9x16B chunks, coprime 8)
//  B: [64 rows][192 halves + 8 pad]  pitch 400B (25x16B chunks, coprime 8)
#define A_PITCH 144
#define B_PITCH 400
#define A_STAGE (BM * A_PITCH)              // 18432
#define B_STAGE (BK * B_PITCH)              // 25600
#define STAGE_BYTES (A_STAGE + B_STAGE)     // 44032
#define SMEM_TOTAL (STAGES * STAGE_BYTES)   // 132096

// Scratch
__device__ __half g_W[(size_t)K_ * N_];   // dequantized fp16 weights [K][N]
__device__ __half g_X[(size_t)M_ * K_];   // fp16 activations [M][K]

// ---------------------------------------------------------------------------
// Helpers
// ---------------------------------------------------------------------------
__device__ __forceinline__ unsigned smem_u32(const void* p) {
    unsigned a;
    asm("{ .reg .u64 t; cvta.to.shared.u64 t, %1; cvt.u32.u64 %0, t; }" : "=r"(a) : "l"(p));
    return a;
}
__device__ __forceinline__ void cp_async16(unsigned dst, const void* src) {
    asm volatile("cp.async.cg.shared.global [%0], [%1], 16;\n" :: "r"(dst), "l"(src));
}
__device__ __forceinline__ void ldsm4(unsigned r[4], unsigned addr) {
    asm volatile("ldmatrix.sync.aligned.m8n8.x4.shared.b16 {%0,%1,%2,%3}, [%4];"
                 : "=r"(r[0]), "=r"(r[1]), "=r"(r[2]), "=r"(r[3]) : "r"(addr));
}
__device__ __forceinline__ void ldsm4t(unsigned r[4], unsigned addr) {
    asm volatile("ldmatrix.sync.aligned.m8n8.x4.trans.shared.b16 {%0,%1,%2,%3}, [%4];"
                 : "=r"(r[0]), "=r"(r[1]), "=r"(r[2]), "=r"(r[3]) : "r"(addr));
}
__device__ __forceinline__ void mma16816(float c[4], const unsigned a[4], const unsigned b[2]) {
    asm volatile(
        "mma.sync.aligned.m16n8k16.row.col.f32.f16.f16.f32 "
        "{%0,%1,%2,%3}, {%4,%5,%6,%7}, {%8,%9}, {%0,%1,%2,%3};\n"
        : "+f"(c[0]), "+f"(c[1]), "+f"(c[2]), "+f"(c[3])
        : "r"(a[0]), "r"(a[1]), "r"(a[2]), "r"(a[3]), "r"(b[0]), "r"(b[1]));
}
__device__ __forceinline__ unsigned pack2(float lo, float hi) {
    __half2 h = __halves2half2(__float2half_rn(lo), __float2half_rn(hi));
    return *reinterpret_cast<unsigned*>(&h);
}

// ---------------------------------------------------------------------------
// Kernel 1: x -> fp16 g_X
// ---------------------------------------------------------------------------
__global__ void round_x_kernel(const float* __restrict__ x) {
    size_t i = ((size_t)blockIdx.x * blockDim.x + threadIdx.x) * 8;
    float4 v0 = *reinterpret_cast<const float4*>(x + i);
    float4 v1 = *reinterpret_cast<const float4*>(x + i + 4);
    uint4 o;
    o.x = pack2(v0.x, v0.y);
    o.y = pack2(v0.z, v0.w);
    o.z = pack2(v1.x, v1.y);
    o.w = pack2(v1.z, v1.w);
    *reinterpret_cast<uint4*>(g_X + i) = o;
}

// ---------------------------------------------------------------------------
// Kernel 2: dequant int4 -> fp16 g_W[K][N]
// ---------------------------------------------------------------------------
__global__ __launch_bounds__(256)
void dequant_kernel(const int* __restrict__ qw,
                    const int* __restrict__ qz,
                    const float* __restrict__ sc) {
    int word = blockIdx.x * blockDim.x + threadIdx.x;   // 0..NW_-1
    int k = blockIdx.y;
    int g = k >> 7;

    int q = qw[(size_t)k * NW_ + word];
    int z = qz[(size_t)g * NW_ + word];
    const float4* s4 = reinterpret_cast<const float4*>(sc + (size_t)g * N_ + (size_t)word * 8);
    float4 sa = s4[0], sb = s4[1];
    float s[8] = {sa.x, sa.y, sa.z, sa.w, sb.x, sb.y, sb.z, sb.w};

    float o[8];
#pragma unroll
    for (int j = 0; j < 8; j++) {
        int wv = (q >> (4 * j)) & 0xF;
        int zv = (z >> (4 * j)) & 0xF;
        o[j] = (float)(wv - zv) * s[j];
    }
    uint4 pk;
    pk.x = pack2(o[0], o[1]);
    pk.y = pack2(o[2], o[3]);
    pk.z = pack2(o[4], o[5]);
    pk.w = pack2(o[6], o[7]);
    *reinterpret_cast<uint4*>(g_W + (size_t)k * N_ + (size_t)word * 8) = pk;
}

// ---------------------------------------------------------------------------
// Kernel 3: fp16 GEMM  out = g_X @ g_W + bias   (fp32 accumulate)
// BK=64, 3 stages, single barrier per k-tile (64 iterations).
// ---------------------------------------------------------------------------
__global__ __launch_bounds__(THREADS, 1)
void gemm_f16_kernel(const float* __restrict__ bias, float* __restrict__ out) {
    extern __shared__ char dsmem[];
    const unsigned smem_base = smem_u32(dsmem);

    const int tid  = threadIdx.x;
    const int lane = tid & 31;
    const int warp = tid >> 5;
    const int wm = warp >> 2;          // 0..1  (64-row slab)
    const int wn = warp & 3;           // 0..3  (48-col slab)

    // L2-friendly CTA swizzle: groups of 8 M-tiles share B panels
    const int PN = N_ / BN;            // 64
    const int GROUP = 8;
    int bid = blockIdx.x;
    int grp = bid / (GROUP * PN);              // 0..3
    int rem = bid % (GROUP * PN);
    int bm = grp * GROUP + (rem % GROUP);      // 0..31
    int bn = rem / GROUP;                      // 0..63

    const __half* Ag = g_X + (size_t)(bm * BM) * K_;
    const __half* Bg = g_W + bn * BN;

    // cp.async assignments
    // A: 128 rows x 8 chunks = 1024 chunks, 4 per thread
    // B: 64 rows x 24 chunks = 1536 chunks; thread t -> row t>>2, 6 chunks
    const int b_row = tid >> 2;
    const int b_c0  = (tid & 3) * 6;

    auto load_tile = [&](int kt) {
        const unsigned so = (unsigned)((kt % STAGES) * STAGE_BYTES);
        const unsigned sa = smem_base + so;
        const unsigned sb = sa + A_STAGE;
#pragma unroll
        for (int i = 0; i < 4; i++) {
            int ch = tid + i * 256;
            int row = ch >> 3, c = ch & 7;
            cp_async16(sa + (unsigned)(row * A_PITCH + c * 16),
                       Ag + (size_t)row * K_ + kt * BK + c * 8);
        }
        const __half* brow = Bg + (size_t)(kt * BK + b_row) * N_;
#pragma unroll
        for (int i = 0; i < 6; i++) {
            int cn = b_c0 + i;
            cp_async16(sb + (unsigned)(b_row * B_PITCH + cn * 16), brow + cn * 8);
        }
    };

    float acc[4][6][4];
#pragma unroll
    for (int mi = 0; mi < 4; mi++)
#pragma unroll
        for (int ni = 0; ni < 6; ni++)
#pragma unroll
            for (int r = 0; r < 4; r++) acc[mi][ni][r] = 0.0f;

    // Per-lane ldmatrix address components
    const unsigned a_lds_row = (unsigned)((wm * 64 + (lane & 15)) * A_PITCH + (lane >> 4) * 16);
    const unsigned b_lds_col = (unsigned)((wn * 48 + (lane >> 4) * 8) * 2);
    const unsigned b_lds_row = (unsigned)((lane & 15) * B_PITCH);

    // Prologue: 2 stages in flight
    load_tile(0); asm volatile("cp.async.commit_group;\n");
    load_tile(1); asm volatile("cp.async.commit_group;\n");

    for (int kt = 0; kt < KTILES; kt++) {
        // Retire tile kt (2 groups in flight -> wait_group 1 completes kt).
        asm volatile("cp.async.wait_group 1;\n" ::: "memory");
        __syncthreads();
        // WAR safe: stage (kt+2)%3 == (kt-1)%3, fully read in compute(kt-1)
        // before every warp passed this barrier.
        if (kt + 2 < KTILES) load_tile(kt + 2);
        asm volatile("cp.async.commit_group;\n");   // empty commit keeps count exact

        const unsigned so = (unsigned)((kt % STAGES) * STAGE_BYTES);
        const unsigned sa = smem_base + so;
        const unsigned sb = sa + A_STAGE;

#pragma unroll
        for (int kk = 0; kk < 4; kk++) {            // four k16 sub-steps
            unsigned af[4][4];
            unsigned bf[6][2];
#pragma unroll
            for (int mi = 0; mi < 4; mi++)
                ldsm4(af[mi], sa + a_lds_row + (unsigned)(mi * 16 * A_PITCH)
                                 + (unsigned)(kk * 32));
#pragma unroll
            for (int nb = 0; nb < 3; nb++) {
                unsigned t[4];
                ldsm4t(t, sb + b_lds_row + (unsigned)(kk * 16 * B_PITCH)
                          + b_lds_col + (unsigned)(nb * 32));
                bf[2 * nb + 0][0] = t[0]; bf[2 * nb + 0][1] = t[1];
                bf[2 * nb + 1][0] = t[2]; bf[2 * nb + 1][1] = t[3];
            }
#pragma unroll
            for (int mi = 0; mi < 4; mi++)
#pragma unroll
                for (int ni = 0; ni < 6; ni++)
                    mma16816(acc[mi][ni], af[mi], bf[ni]);
        }
    }

    // Epilogue: bias add, fp32 stores
    const int row_base = bm * BM + wm * 64 + (lane >> 2);
    const int col_base = bn * BN + wn * 48 + (lane & 3) * 2;
#pragma unroll
    for (int mi = 0; mi < 4; mi++) {
        int row = row_base + mi * 16;
#pragma unroll
        for (int ni = 0; ni < 6; ni++) {
            int col = col_base + ni * 8;
            float2 bv = *reinterpret_cast<const float2*>(bias + col);
            float2 o0 = make_float2(acc[mi][ni][0] + bv.x, acc[mi][ni][1] + bv.y);
            float2 o1 = make_float2(acc[mi][ni][2] + bv.x, acc[mi][ni][3] + bv.y);
            *reinterpret_cast<float2*>(out + (size_t)row * N_ + col) = o0;
            *reinterpret_cast<float2*>(out + (size_t)(row + 8) * N_ + col) = o1;
        }
    }
}

// ---------------------------------------------------------------------------
extern "C" void kernel_launch(void* const* d_in, const int* in_sizes, int n_in,
                              void* d_out, int out_size) {
    const float* x    = (const float*)d_in[0];
    const int*   qw   = (const int*)d_in[1];
    const int*   qz   = (const int*)d_in[2];
    const float* sc   = (const float*)d_in[3];
    const float* bias = (const float*)d_in[4];
    float* out = (float*)d_out;

    // 1) x -> fp16
    round_x_kernel<<<(M_ * (size_t)K_) / 8 / 256, 256>>>(x);
    // 2) dequantize weights -> fp16 g_W[K][N]
    dequant_kernel<<<dim3(NW_ / 256, K_), 256>>>(qw, qz, sc);
    // 3) fp16 tensor-core GEMM + bias
    cudaFuncSetAttribute(gemm_f16_kernel,
                         cudaFuncAttributeMaxDynamicSharedMemorySize, SMEM_TOTAL);
    gemm_f16_kernel<<<(M_ / BM) * (N_ / BN), THREADS, SMEM_TOTAL>>>(bias, out);
}

// round 14
// speedup vs baseline: 1.2979x; 1.2979x over previous
#include <cuda_runtime.h>
#include <cuda_fp16.h>
#include <cstdint>

// ---------------------------------------------------------------------------
// Problem constants
// ---------------------------------------------------------------------------
#define M_ 4096
#define N_ 12288
#define K_ 4096
#define NW_ (N_ / 8)          // packed int32 words per k-row = 1536

// ---------------------------------------------------------------------------
// GEMM tiling: CTA 128x192x64, 8 warps (2x4), warp tile 64x48, mma.m16n8k16
// Grid 32x64 = 2048 CTAs -> 13.84 waves (tail 1.2% vs 5.6% at BN=256)
// ---------------------------------------------------------------------------
#define BM 128
#define BN 192
#define BK 64
#define STAGES 3
#define KTILES (K_ / BK)        // 64
#define THREADS 256

// SMEM layout per stage (fp16):
//  A: [128 rows][64 halves + 8 pad]  pitch 144B (9x16B chunks, coprime 8)
//  B: [64 rows][192 halves + 8 pad]  pitch 400B (25x16B chunks, coprime 8)
#define A_PITCH 144
#define B_PITCH 400
#define A_STAGE (BM * A_PITCH)              // 18432
#define B_STAGE (BK * B_PITCH)              // 25600
#define STAGE_BYTES (A_STAGE + B_STAGE)     // 44032
#define SMEM_TOTAL (STAGES * STAGE_BYTES)   // 132096

// Scratch
__device__ __half g_W[(size_t)K_ * N_];   // dequantized fp16 weights [K][N]
__device__ __half g_X[(size_t)M_ * K_];   // fp16 activations [M][K]

// ---------------------------------------------------------------------------
// Helpers
// ---------------------------------------------------------------------------
__device__ __forceinline__ unsigned smem_u32(const void* p) {
    unsigned a;
    asm("{ .reg .u64 t; cvta.to.shared.u64 t, %1; cvt.u32.u64 %0, t; }" : "=r"(a) : "l"(p));
    return a;
}
__device__ __forceinline__ void cp_async16(unsigned dst, const void* src) {
    asm volatile("cp.async.cg.shared.global [%0], [%1], 16;\n" :: "r"(dst), "l"(src));
}
__device__ __forceinline__ void ldsm4(unsigned r[4], unsigned addr) {
    asm volatile("ldmatrix.sync.aligned.m8n8.x4.shared.b16 {%0,%1,%2,%3}, [%4];"
                 : "=r"(r[0]), "=r"(r[1]), "=r"(r[2]), "=r"(r[3]) : "r"(addr));
}
__device__ __forceinline__ void ldsm4t(unsigned r[4], unsigned addr) {
    asm volatile("ldmatrix.sync.aligned.m8n8.x4.trans.shared.b16 {%0,%1,%2,%3}, [%4];"
                 : "=r"(r[0]), "=r"(r[1]), "=r"(r[2]), "=r"(r[3]) : "r"(addr));
}
__device__ __forceinline__ void mma16816(float c[4], const unsigned a[4], const unsigned b[2]) {
    asm volatile(
        "mma.sync.aligned.m16n8k16.row.col.f32.f16.f16.f32 "
        "{%0,%1,%2,%3}, {%4,%5,%6,%7}, {%8,%9}, {%0,%1,%2,%3};\n"
        : "+f"(c[0]), "+f"(c[1]), "+f"(c[2]), "+f"(c[3])
        : "r"(a[0]), "r"(a[1]), "r"(a[2]), "r"(a[3]), "r"(b[0]), "r"(b[1]));
}
__device__ __forceinline__ unsigned pack2(float lo, float hi) {
    __half2 h = __halves2half2(__float2half_rn(lo), __float2half_rn(hi));
    return *reinterpret_cast<unsigned*>(&h);
}

// ---------------------------------------------------------------------------
// Kernel 1: x -> fp16 g_X
// ---------------------------------------------------------------------------
__global__ void round_x_kernel(const float* __restrict__ x) {
    size_t i = ((size_t)blockIdx.x * blockDim.x + threadIdx.x) * 8;
    float4 v0 = *reinterpret_cast<const float4*>(x + i);
    float4 v1 = *reinterpret_cast<const float4*>(x + i + 4);
    uint4 o;
    o.x = pack2(v0.x, v0.y);
    o.y = pack2(v0.z, v0.w);
    o.z = pack2(v1.x, v1.y);
    o.w = pack2(v1.z, v1.w);
    *reinterpret_cast<uint4*>(g_X + i) = o;
}

// ---------------------------------------------------------------------------
// Kernel 2: dequant int4 -> fp16 g_W[K][N]
// ---------------------------------------------------------------------------
__global__ __launch_bounds__(256)
void dequant_kernel(const int* __restrict__ qw,
                    const int* __restrict__ qz,
                    const float* __restrict__ sc) {
    int word = blockIdx.x * blockDim.x + threadIdx.x;   // 0..NW_-1
    int k = blockIdx.y;
    int g = k >> 7;

    int q = qw[(size_t)k * NW_ + word];
    int z = qz[(size_t)g * NW_ + word];
    const float4* s4 = reinterpret_cast<const float4*>(sc + (size_t)g * N_ + (size_t)word * 8);
    float4 sa = s4[0], sb = s4[1];
    float s[8] = {sa.x, sa.y, sa.z, sa.w, sb.x, sb.y, sb.z, sb.w};

    float o[8];
#pragma unroll
    for (int j = 0; j < 8; j++) {
        int wv = (q >> (4 * j)) & 0xF;
        int zv = (z >> (4 * j)) & 0xF;
        o[j] = (float)(wv - zv) * s[j];
    }
    uint4 pk;
    pk.x = pack2(o[0], o[1]);
    pk.y = pack2(o[2], o[3]);
    pk.z = pack2(o[4], o[5]);
    pk.w = pack2(o[6], o[7]);
    *reinterpret_cast<uint4*>(g_W + (size_t)k * N_ + (size_t)word * 8) = pk;
}

// ---------------------------------------------------------------------------
// Kernel 3: fp16 GEMM  out = g_X @ g_W + bias   (fp32 accumulate)
// BK=64, 3 stages, single barrier per k-tile (64 iterations).
// ---------------------------------------------------------------------------
__global__ __launch_bounds__(THREADS, 1)
void gemm_f16_kernel(const float* __restrict__ bias, float* __restrict__ out) {
    extern __shared__ char dsmem[];
    const unsigned smem_base = smem_u32(dsmem);

    const int tid  = threadIdx.x;
    const int lane = tid & 31;
    const int warp = tid >> 5;
    const int wm = warp >> 2;          // 0..1  (64-row slab)
    const int wn = warp & 3;           // 0..3  (48-col slab)

    // L2-friendly CTA swizzle: groups of 8 M-tiles share B panels
    const int PN = N_ / BN;            // 64
    const int GROUP = 8;
    int bid = blockIdx.x;
    int grp = bid / (GROUP * PN);              // 0..3
    int rem = bid % (GROUP * PN);
    int bm = grp * GROUP + (rem % GROUP);      // 0..31
    int bn = rem / GROUP;                      // 0..63

    const __half* Ag = g_X + (size_t)(bm * BM) * K_;
    const __half* Bg = g_W + bn * BN;

    auto load_tile = [&](int kt) {
        const unsigned so = (unsigned)((kt % STAGES) * STAGE_BYTES);
        const unsigned sa = smem_base + so;
        const unsigned sb = sa + A_STAGE;
        // A: 128 rows x 8 chunks = 1024 chunks, 4 per thread (coalesced:
        // warp covers 4 full rows, 8 contiguous chunks each)
#pragma unroll
        for (int i = 0; i < 4; i++) {
            int ch = tid + i * 256;
            int row = ch >> 3, c = ch & 7;
            cp_async16(sa + (unsigned)(row * A_PITCH + c * 16),
                       Ag + (size_t)row * K_ + kt * BK + c * 8);
        }
        // B: 64 rows x 24 chunks = 1536 chunks; LINEAR mapping so consecutive
        // lanes hit consecutive chunks (contiguous 384B runs -> coalesced)
#pragma unroll
        for (int i = 0; i < 6; i++) {
            int ch = tid + i * 256;
            int row = ch / 24, cn = ch % 24;
            cp_async16(sb + (unsigned)(row * B_PITCH + cn * 16),
                       Bg + (size_t)(kt * BK + row) * N_ + cn * 8);
        }
    };

    float acc[4][6][4];
#pragma unroll
    for (int mi = 0; mi < 4; mi++)
#pragma unroll
        for (int ni = 0; ni < 6; ni++)
#pragma unroll
            for (int r = 0; r < 4; r++) acc[mi][ni][r] = 0.0f;

    // Per-lane ldmatrix address components
    const unsigned a_lds_row = (unsigned)((wm * 64 + (lane & 15)) * A_PITCH + (lane >> 4) * 16);
    const unsigned b_lds_col = (unsigned)((wn * 48 + (lane >> 4) * 8) * 2);
    const unsigned b_lds_row = (unsigned)((lane & 15) * B_PITCH);

    // Prologue: 2 stages in flight
    load_tile(0); asm volatile("cp.async.commit_group;\n");
    load_tile(1); asm volatile("cp.async.commit_group;\n");

    for (int kt = 0; kt < KTILES; kt++) {
        // Retire tile kt (2 groups in flight -> wait_group 1 completes kt).
        asm volatile("cp.async.wait_group 1;\n" ::: "memory");
        __syncthreads();
        // WAR safe: stage (kt+2)%3 == (kt-1)%3, fully read in compute(kt-1)
        // before every warp passed this barrier.
        if (kt + 2 < KTILES) load_tile(kt + 2);
        asm volatile("cp.async.commit_group;\n");   // empty commit keeps count exact

        const unsigned so = (unsigned)((kt % STAGES) * STAGE_BYTES);
        const unsigned sa = smem_base + so;
        const unsigned sb = sa + A_STAGE;

#pragma unroll
        for (int kk = 0; kk < 4; kk++) {            // four k16 sub-steps
            unsigned af[4][4];
            unsigned bf[6][2];
#pragma unroll
            for (int mi = 0; mi < 4; mi++)
                ldsm4(af[mi], sa + a_lds_row + (unsigned)(mi * 16 * A_PITCH)
                                 + (unsigned)(kk * 32));
#pragma unroll
            for (int nb = 0; nb < 3; nb++) {
                unsigned t[4];
                ldsm4t(t, sb + b_lds_row + (unsigned)(kk * 16 * B_PITCH)
                          + b_lds_col + (unsigned)(nb * 32));
                bf[2 * nb + 0][0] = t[0]; bf[2 * nb + 0][1] = t[1];
                bf[2 * nb + 1][0] = t[2]; bf[2 * nb + 1][1] = t[3];
            }
#pragma unroll
            for (int mi = 0; mi < 4; mi++)
#pragma unroll
                for (int ni = 0; ni < 6; ni++)
                    mma16816(acc[mi][ni], af[mi], bf[ni]);
        }
    }

    // Epilogue: bias add, fp32 stores
    const int row_base = bm * BM + wm * 64 + (lane >> 2);
    const int col_base = bn * BN + wn * 48 + (lane & 3) * 2;
#pragma unroll
    for (int mi = 0; mi < 4; mi++) {
        int row = row_base + mi * 16;
#pragma unroll
        for (int ni = 0; ni < 6; ni++) {
            int col = col_base + ni * 8;
            float2 bv = *reinterpret_cast<const float2*>(bias + col);
            float2 o0 = make_float2(acc[mi][ni][0] + bv.x, acc[mi][ni][1] + bv.y);
            float2 o1 = make_float2(acc[mi][ni][2] + bv.x, acc[mi][ni][3] + bv.y);
            *reinterpret_cast<float2*>(out + (size_t)row * N_ + col) = o0;
            *reinterpret_cast<float2*>(out + (size_t)(row + 8) * N_ + col) = o1;
        }
    }
}

// ---------------------------------------------------------------------------
extern "C" void kernel_launch(void* const* d_in, const int* in_sizes, int n_in,
                              void* d_out, int out_size) {
    const float* x    = (const float*)d_in[0];
    const int*   qw   = (const int*)d_in[1];
    const int*   qz   = (const int*)d_in[2];
    const float* sc   = (const float*)d_in[3];
    const float* bias = (const float*)d_in[4];
    float* out = (float*)d_out;

    // 1) x -> fp16
    round_x_kernel<<<(M_ * (size_t)K_) / 8 / 256, 256>>>(x);
    // 2) dequantize weights -> fp16 g_W[K][N]
    dequant_kernel<<<dim3(NW_ / 256, K_), 256>>>(qw, qz, sc);
    // 3) fp16 tensor-core GEMM + bias
    cudaFuncSetAttribute(gemm_f16_kernel,
                         cudaFuncAttributeMaxDynamicSharedMemorySize, SMEM_TOTAL);
    gemm_f16_kernel<<<(M_ / BM) * (N_ / BN), THREADS, SMEM_TOTAL>>>(bias, out);
}

// round 15
// speedup vs baseline: 1.3336x; 1.0275x over previous
#include <cuda_runtime.h>
#include <cuda_fp16.h>
#include <cstdint>

// ---------------------------------------------------------------------------
// Problem constants
// ---------------------------------------------------------------------------
#define M_ 4096
#define N_ 12288
#define K_ 4096
#define NW_ (N_ / 8)          // packed int32 words per k-row = 1536

// ---------------------------------------------------------------------------
// GEMM tiling: CTA 128x256x64, 8 warps (2x4), warp tile 64x64, mma.m16n8k16
// R11 base (best: 1275us) + STAGES 3->4 for latency-jitter absorption.
// ---------------------------------------------------------------------------
#define BM 128
#define BN 256
#define BK 64
#define STAGES 4
#define KTILES (K_ / BK)        // 64
#define THREADS 256

// SMEM layout per stage (fp16):
//  A: [128 rows][64 halves + 8 pad]  pitch 144B (9x16B chunks, coprime 8)
//  B: [64 rows][256 halves + 8 pad]  pitch 528B (33x16B chunks, coprime 8)
#define A_PITCH 144
#define B_PITCH 528
#define A_STAGE (BM * A_PITCH)              // 18432
#define B_STAGE (BK * B_PITCH)              // 33792
#define STAGE_BYTES (A_STAGE + B_STAGE)     // 52224
#define SMEM_TOTAL (STAGES * STAGE_BYTES)   // 208896 (<= 227KB)

// Scratch
__device__ __half g_W[(size_t)K_ * N_];   // dequantized fp16 weights [K][N]
__device__ __half g_X[(size_t)M_ * K_];   // fp16 activations [M][K]

// ---------------------------------------------------------------------------
// Helpers
// ---------------------------------------------------------------------------
__device__ __forceinline__ unsigned smem_u32(const void* p) {
    unsigned a;
    asm("{ .reg .u64 t; cvta.to.shared.u64 t, %1; cvt.u32.u64 %0, t; }" : "=r"(a) : "l"(p));
    return a;
}
__device__ __forceinline__ void cp_async16(unsigned dst, const void* src) {
    asm volatile("cp.async.cg.shared.global [%0], [%1], 16;\n" :: "r"(dst), "l"(src));
}
__device__ __forceinline__ void ldsm4(unsigned r[4], unsigned addr) {
    asm volatile("ldmatrix.sync.aligned.m8n8.x4.shared.b16 {%0,%1,%2,%3}, [%4];"
                 : "=r"(r[0]), "=r"(r[1]), "=r"(r[2]), "=r"(r[3]) : "r"(addr));
}
__device__ __forceinline__ void ldsm4t(unsigned r[4], unsigned addr) {
    asm volatile("ldmatrix.sync.aligned.m8n8.x4.trans.shared.b16 {%0,%1,%2,%3}, [%4];"
                 : "=r"(r[0]), "=r"(r[1]), "=r"(r[2]), "=r"(r[3]) : "r"(addr));
}
__device__ __forceinline__ void mma16816(float c[4], const unsigned a[4], const unsigned b[2]) {
    asm volatile(
        "mma.sync.aligned.m16n8k16.row.col.f32.f16.f16.f32 "
        "{%0,%1,%2,%3}, {%4,%5,%6,%7}, {%8,%9}, {%0,%1,%2,%3};\n"
        : "+f"(c[0]), "+f"(c[1]), "+f"(c[2]), "+f"(c[3])
        : "r"(a[0]), "r"(a[1]), "r"(a[2]), "r"(a[3]), "r"(b[0]), "r"(b[1]));
}
__device__ __forceinline__ unsigned pack2(float lo, float hi) {
    __half2 h = __halves2half2(__float2half_rn(lo), __float2half_rn(hi));
    return *reinterpret_cast<unsigned*>(&h);
}

// ---------------------------------------------------------------------------
// Kernel 1: x -> fp16 g_X
// ---------------------------------------------------------------------------
__global__ void round_x_kernel(const float* __restrict__ x) {
    size_t i = ((size_t)blockIdx.x * blockDim.x + threadIdx.x) * 8;
    float4 v0 = *reinterpret_cast<const float4*>(x + i);
    float4 v1 = *reinterpret_cast<const float4*>(x + i + 4);
    uint4 o;
    o.x = pack2(v0.x, v0.y);
    o.y = pack2(v0.z, v0.w);
    o.z = pack2(v1.x, v1.y);
    o.w = pack2(v1.z, v1.w);
    *reinterpret_cast<uint4*>(g_X + i) = o;
}

// ---------------------------------------------------------------------------
// Kernel 2: dequant int4 -> fp16 g_W[K][N]
// ---------------------------------------------------------------------------
__global__ __launch_bounds__(256)
void dequant_kernel(const int* __restrict__ qw,
                    const int* __restrict__ qz,
                    const float* __restrict__ sc) {
    int word = blockIdx.x * blockDim.x + threadIdx.x;   // 0..NW_-1
    int k = blockIdx.y;
    int g = k >> 7;

    int q = qw[(size_t)k * NW_ + word];
    int z = qz[(size_t)g * NW_ + word];
    const float4* s4 = reinterpret_cast<const float4*>(sc + (size_t)g * N_ + (size_t)word * 8);
    float4 sa = s4[0], sb = s4[1];
    float s[8] = {sa.x, sa.y, sa.z, sa.w, sb.x, sb.y, sb.z, sb.w};

    float o[8];
#pragma unroll
    for (int j = 0; j < 8; j++) {
        int wv = (q >> (4 * j)) & 0xF;
        int zv = (z >> (4 * j)) & 0xF;
        o[j] = (float)(wv - zv) * s[j];
    }
    uint4 pk;
    pk.x = pack2(o[0], o[1]);
    pk.y = pack2(o[2], o[3]);
    pk.z = pack2(o[4], o[5]);
    pk.w = pack2(o[6], o[7]);
    *reinterpret_cast<uint4*>(g_W + (size_t)k * N_ + (size_t)word * 8) = pk;
}

// ---------------------------------------------------------------------------
// Kernel 3: fp16 GEMM  out = g_X @ g_W + bias   (fp32 accumulate)
// BK=64, 4 stages, single barrier per k-tile (64 iterations).
// ---------------------------------------------------------------------------
__global__ __launch_bounds__(THREADS, 1)
void gemm_f16_kernel(const float* __restrict__ bias, float* __restrict__ out) {
    extern __shared__ char dsmem[];
    const unsigned smem_base = smem_u32(dsmem);

    const int tid  = threadIdx.x;
    const int lane = tid & 31;
    const int warp = tid >> 5;
    const int wm = warp >> 2;          // 0..1  (64-row slab)
    const int wn = warp & 3;           // 0..3  (64-col slab)

    // L2-friendly CTA swizzle: groups of 8 M-tiles share B panels
    const int PN = N_ / BN;            // 48
    const int GROUP = 8;
    int bid = blockIdx.x;
    int grp = bid / (GROUP * PN);
    int rem = bid % (GROUP * PN);
    int bm = grp * GROUP + (rem % GROUP);   // 0..31
    int bn = rem / GROUP;                   // 0..47

    const __half* Ag = g_X + (size_t)(bm * BM) * K_;
    const __half* Bg = g_W + bn * BN;

    auto load_tile = [&](int kt) {
        const unsigned so = (unsigned)((kt & (STAGES - 1)) * STAGE_BYTES);
        const unsigned sa = smem_base + so;
        const unsigned sb = sa + A_STAGE;
        // A: 128 rows x 8 chunks = 1024 chunks, 4 per thread
#pragma unroll
        for (int i = 0; i < 4; i++) {
            int ch = tid + i * 256;
            int row = ch >> 3, c = ch & 7;
            cp_async16(sa + (unsigned)(row * A_PITCH + c * 16),
                       Ag + (size_t)row * K_ + kt * BK + c * 8);
        }
        // B: 64 rows x 32 chunks = 2048 chunks, 8 per thread
#pragma unroll
        for (int i = 0; i < 8; i++) {
            int ch = tid + i * 256;
            int row = ch >> 5, cn = ch & 31;
            cp_async16(sb + (unsigned)(row * B_PITCH + cn * 16),
                       Bg + (size_t)(kt * BK + row) * N_ + cn * 8);
        }
    };

    float acc[4][8][4];
#pragma unroll
    for (int mi = 0; mi < 4; mi++)
#pragma unroll
        for (int ni = 0; ni < 8; ni++)
#pragma unroll
            for (int r = 0; r < 4; r++) acc[mi][ni][r] = 0.0f;

    // Per-lane ldmatrix address components
    const unsigned a_lds_row = (unsigned)((wm * 64 + (lane & 15)) * A_PITCH + (lane >> 4) * 16);
    const unsigned b_lds_col = (unsigned)((wn * 64 + (lane >> 4) * 8) * 2);
    const unsigned b_lds_row = (unsigned)((lane & 15) * B_PITCH);

    // Prologue: 3 stages in flight
    load_tile(0); asm volatile("cp.async.commit_group;\n");
    load_tile(1); asm volatile("cp.async.commit_group;\n");
    load_tile(2); asm volatile("cp.async.commit_group;\n");

    for (int kt = 0; kt < KTILES; kt++) {
        // Retire tile kt (3 groups in flight -> wait_group 2 completes kt).
        asm volatile("cp.async.wait_group 2;\n" ::: "memory");
        __syncthreads();
        // WAR safe: stage (kt+3)%4 == (kt-1)%4, fully read in compute(kt-1)
        // before every warp passed this barrier.
        if (kt + 3 < KTILES) load_tile(kt + 3);
        asm volatile("cp.async.commit_group;\n");   // empty commit keeps count exact

        const unsigned so = (unsigned)((kt & (STAGES - 1)) * STAGE_BYTES);
        const unsigned sa = smem_base + so;
        const unsigned sb = sa + A_STAGE;

#pragma unroll
        for (int kk = 0; kk < 4; kk++) {            // four k16 sub-steps
            unsigned af[4][4];
            unsigned bf[8][2];
#pragma unroll
            for (int mi = 0; mi < 4; mi++)
                ldsm4(af[mi], sa + a_lds_row + (unsigned)(mi * 16 * A_PITCH)
                                 + (unsigned)(kk * 32));
#pragma unroll
            for (int nb = 0; nb < 4; nb++) {
                unsigned t[4];
                ldsm4t(t, sb + b_lds_row + (unsigned)(kk * 16 * B_PITCH)
                          + b_lds_col + (unsigned)(nb * 32));
                bf[2 * nb + 0][0] = t[0]; bf[2 * nb + 0][1] = t[1];
                bf[2 * nb + 1][0] = t[2]; bf[2 * nb + 1][1] = t[3];
            }
#pragma unroll
            for (int mi = 0; mi < 4; mi++)
#pragma unroll
                for (int ni = 0; ni < 8; ni++)
                    mma16816(acc[mi][ni], af[mi], bf[ni]);
        }
    }

    // Epilogue: bias add, fp32 stores
    const int row_base = bm * BM + wm * 64 + (lane >> 2);
    const int col_base = bn * BN + wn * 64 + (lane & 3) * 2;
#pragma unroll
    for (int mi = 0; mi < 4; mi++) {
        int row = row_base + mi * 16;
#pragma unroll
        for (int ni = 0; ni < 8; ni++) {
            int col = col_base + ni * 8;
            float2 bv = *reinterpret_cast<const float2*>(bias + col);
            float2 o0 = make_float2(acc[mi][ni][0] + bv.x, acc[mi][ni][1] + bv.y);
            float2 o1 = make_float2(acc[mi][ni][2] + bv.x, acc[mi][ni][3] + bv.y);
            *reinterpret_cast<float2*>(out + (size_t)row * N_ + col) = o0;
            *reinterpret_cast<float2*>(out + (size_t)(row + 8) * N_ + col) = o1;
        }
    }
}

// ---------------------------------------------------------------------------
extern "C" void kernel_launch(void* const* d_in, const int* in_sizes, int n_in,
                              void* d_out, int out_size) {
    const float* x    = (const float*)d_in[0];
    const int*   qw   = (const int*)d_in[1];
    const int*   qz   = (const int*)d_in[2];
    const float* sc   = (const float*)d_in[3];
    const float* bias = (const float*)d_in[4];
    float* out = (float*)d_out;

    // 1) x -> fp16
    round_x_kernel<<<(M_ * (size_t)K_) / 8 / 256, 256>>>(x);
    // 2) dequantize weights -> fp16 g_W[K][N]
    dequant_kernel<<<dim3(NW_ / 256, K_), 256>>>(qw, qz, sc);
    // 3) fp16 tensor-core GEMM + bias
    cudaFuncSetAttribute(gemm_f16_kernel,
                         cudaFuncAttributeMaxDynamicSharedMemorySize, SMEM_TOTAL);
    gemm_f16_kernel<<<(M_ / BM) * (N_ / BN), THREADS, SMEM_TOTAL>>>(bias, out);
}

// round 16
// speedup vs baseline: 1.3361x; 1.0019x over previous
#include <cuda_runtime.h>
#include <cuda_fp16.h>
#include <cstdint>

// ---------------------------------------------------------------------------
// Problem constants
// ---------------------------------------------------------------------------
#define M_ 4096
#define N_ 12288
#define K_ 4096
#define NW_ (N_ / 8)          // packed int32 words per k-row = 1536

// ---------------------------------------------------------------------------
// GEMM tiling: CTA 128x256x64, 16 warps (4x4), warp tile 32x64, mma.m16n8k16
// 4 warps/SMSP for latency coverage (vs 2 at 256 threads).
// ---------------------------------------------------------------------------
#define BM 128
#define BN 256
#define BK 64
#define STAGES 4
#define KTILES (K_ / BK)        // 64
#define THREADS 512

// SMEM layout per stage (fp16):
//  A: [128 rows][64 halves + 8 pad]  pitch 144B (9x16B chunks, coprime 8)
//  B: [64 rows][256 halves + 8 pad]  pitch 528B (33x16B chunks, coprime 8)
#define A_PITCH 144
#define B_PITCH 528
#define A_STAGE (BM * A_PITCH)              // 18432
#define B_STAGE (BK * B_PITCH)              // 33792
#define STAGE_BYTES (A_STAGE + B_STAGE)     // 52224
#define SMEM_TOTAL (STAGES * STAGE_BYTES)   // 208896 (<= 227KB)

// Scratch
__device__ __half g_W[(size_t)K_ * N_];   // dequantized fp16 weights [K][N]
__device__ __half g_X[(size_t)M_ * K_];   // fp16 activations [M][K]

// ---------------------------------------------------------------------------
// Helpers
// ---------------------------------------------------------------------------
__device__ __forceinline__ unsigned smem_u32(const void* p) {
    unsigned a;
    asm("{ .reg .u64 t; cvta.to.shared.u64 t, %1; cvt.u32.u64 %0, t; }" : "=r"(a) : "l"(p));
    return a;
}
__device__ __forceinline__ void cp_async16(unsigned dst, const void* src) {
    asm volatile("cp.async.cg.shared.global [%0], [%1], 16;\n" :: "r"(dst), "l"(src));
}
__device__ __forceinline__ void ldsm4(unsigned r[4], unsigned addr) {
    asm volatile("ldmatrix.sync.aligned.m8n8.x4.shared.b16 {%0,%1,%2,%3}, [%4];"
                 : "=r"(r[0]), "=r"(r[1]), "=r"(r[2]), "=r"(r[3]) : "r"(addr));
}
__device__ __forceinline__ void ldsm4t(unsigned r[4], unsigned addr) {
    asm volatile("ldmatrix.sync.aligned.m8n8.x4.trans.shared.b16 {%0,%1,%2,%3}, [%4];"
                 : "=r"(r[0]), "=r"(r[1]), "=r"(r[2]), "=r"(r[3]) : "r"(addr));
}
__device__ __forceinline__ void mma16816(float c[4], const unsigned a[4], const unsigned b[2]) {
    asm volatile(
        "mma.sync.aligned.m16n8k16.row.col.f32.f16.f16.f32 "
        "{%0,%1,%2,%3}, {%4,%5,%6,%7}, {%8,%9}, {%0,%1,%2,%3};\n"
        : "+f"(c[0]), "+f"(c[1]), "+f"(c[2]), "+f"(c[3])
        : "r"(a[0]), "r"(a[1]), "r"(a[2]), "r"(a[3]), "r"(b[0]), "r"(b[1]));
}
__device__ __forceinline__ unsigned pack2(float lo, float hi) {
    __half2 h = __halves2half2(__float2half_rn(lo), __float2half_rn(hi));
    return *reinterpret_cast<unsigned*>(&h);
}

// ---------------------------------------------------------------------------
// Kernel 1: x -> fp16 g_X
// ---------------------------------------------------------------------------
__global__ void round_x_kernel(const float* __restrict__ x) {
    size_t i = ((size_t)blockIdx.x * blockDim.x + threadIdx.x) * 8;
    float4 v0 = *reinterpret_cast<const float4*>(x + i);
    float4 v1 = *reinterpret_cast<const float4*>(x + i + 4);
    uint4 o;
    o.x = pack2(v0.x, v0.y);
    o.y = pack2(v0.z, v0.w);
    o.z = pack2(v1.x, v1.y);
    o.w = pack2(v1.z, v1.w);
    *reinterpret_cast<uint4*>(g_X + i) = o;
}

// ---------------------------------------------------------------------------
// Kernel 2: dequant int4 -> fp16 g_W[K][N]
// ---------------------------------------------------------------------------
__global__ __launch_bounds__(256)
void dequant_kernel(const int* __restrict__ qw,
                    const int* __restrict__ qz,
                    const float* __restrict__ sc) {
    int word = blockIdx.x * blockDim.x + threadIdx.x;   // 0..NW_-1
    int k = blockIdx.y;
    int g = k >> 7;

    int q = qw[(size_t)k * NW_ + word];
    int z = qz[(size_t)g * NW_ + word];
    const float4* s4 = reinterpret_cast<const float4*>(sc + (size_t)g * N_ + (size_t)word * 8);
    float4 sa = s4[0], sb = s4[1];
    float s[8] = {sa.x, sa.y, sa.z, sa.w, sb.x, sb.y, sb.z, sb.w};

    float o[8];
#pragma unroll
    for (int j = 0; j < 8; j++) {
        int wv = (q >> (4 * j)) & 0xF;
        int zv = (z >> (4 * j)) & 0xF;
        o[j] = (float)(wv - zv) * s[j];
    }
    uint4 pk;
    pk.x = pack2(o[0], o[1]);
    pk.y = pack2(o[2], o[3]);
    pk.z = pack2(o[4], o[5]);
    pk.w = pack2(o[6], o[7]);
    *reinterpret_cast<uint4*>(g_W + (size_t)k * N_ + (size_t)word * 8) = pk;
}

// ---------------------------------------------------------------------------
// Kernel 3: fp16 GEMM  out = g_X @ g_W + bias   (fp32 accumulate)
// BK=64, 4 stages, single barrier per k-tile, 16 warps.
// ---------------------------------------------------------------------------
__global__ __launch_bounds__(THREADS, 1)
void gemm_f16_kernel(const float* __restrict__ bias, float* __restrict__ out) {
    extern __shared__ char dsmem[];
    const unsigned smem_base = smem_u32(dsmem);

    const int tid  = threadIdx.x;
    const int lane = tid & 31;
    const int warp = tid >> 5;
    const int wm = warp >> 2;          // 0..3  (32-row slab)
    const int wn = warp & 3;           // 0..3  (64-col slab)

    // L2-friendly CTA swizzle: groups of 8 M-tiles share B panels
    const int PN = N_ / BN;            // 48
    const int GROUP = 8;
    int bid = blockIdx.x;
    int grp = bid / (GROUP * PN);
    int rem = bid % (GROUP * PN);
    int bm = grp * GROUP + (rem % GROUP);   // 0..31
    int bn = rem / GROUP;                   // 0..47

    const __half* Ag = g_X + (size_t)(bm * BM) * K_;
    const __half* Bg = g_W + bn * BN;

    auto load_tile = [&](int kt) {
        const unsigned so = (unsigned)((kt & (STAGES - 1)) * STAGE_BYTES);
        const unsigned sa = smem_base + so;
        const unsigned sb = sa + A_STAGE;
        // A: 128 rows x 8 chunks = 1024 chunks, 2 per thread
#pragma unroll
        for (int i = 0; i < 2; i++) {
            int ch = tid + i * 512;
            int row = ch >> 3, c = ch & 7;
            cp_async16(sa + (unsigned)(row * A_PITCH + c * 16),
                       Ag + (size_t)row * K_ + kt * BK + c * 8);
        }
        // B: 64 rows x 32 chunks = 2048 chunks, 4 per thread
#pragma unroll
        for (int i = 0; i < 4; i++) {
            int ch = tid + i * 512;
            int row = ch >> 5, cn = ch & 31;
            cp_async16(sb + (unsigned)(row * B_PITCH + cn * 16),
                       Bg + (size_t)(kt * BK + row) * N_ + cn * 8);
        }
    };

    float acc[2][8][4];
#pragma unroll
    for (int mi = 0; mi < 2; mi++)
#pragma unroll
        for (int ni = 0; ni < 8; ni++)
#pragma unroll
            for (int r = 0; r < 4; r++) acc[mi][ni][r] = 0.0f;

    // Per-lane ldmatrix address components
    const unsigned a_lds_row = (unsigned)((wm * 32 + (lane & 15)) * A_PITCH + (lane >> 4) * 16);
    const unsigned b_lds_col = (unsigned)((wn * 64 + (lane >> 4) * 8) * 2);
    const unsigned b_lds_row = (unsigned)((lane & 15) * B_PITCH);

    // Prologue: 3 stages in flight
    load_tile(0); asm volatile("cp.async.commit_group;\n");
    load_tile(1); asm volatile("cp.async.commit_group;\n");
    load_tile(2); asm volatile("cp.async.commit_group;\n");

    for (int kt = 0; kt < KTILES; kt++) {
        // Retire tile kt (3 groups in flight -> wait_group 2 completes kt).
        asm volatile("cp.async.wait_group 2;\n" ::: "memory");
        __syncthreads();
        // WAR safe: stage (kt+3)%4 == (kt-1)%4, fully read in compute(kt-1)
        // before every warp passed this barrier.
        if (kt + 3 < KTILES) load_tile(kt + 3);
        asm volatile("cp.async.commit_group;\n");   // empty commit keeps count exact

        const unsigned so = (unsigned)((kt & (STAGES - 1)) * STAGE_BYTES);
        const unsigned sa = smem_base + so;
        const unsigned sb = sa + A_STAGE;

#pragma unroll
        for (int kk = 0; kk < 4; kk++) {            // four k16 sub-steps
            unsigned af[2][4];
            unsigned bf[8][2];
#pragma unroll
            for (int mi = 0; mi < 2; mi++)
                ldsm4(af[mi], sa + a_lds_row + (unsigned)(mi * 16 * A_PITCH)
                                 + (unsigned)(kk * 32));
#pragma unroll
            for (int nb = 0; nb < 4; nb++) {
                unsigned t[4];
                ldsm4t(t, sb + b_lds_row + (unsigned)(kk * 16 * B_PITCH)
                          + b_lds_col + (unsigned)(nb * 32));
                bf[2 * nb + 0][0] = t[0]; bf[2 * nb + 0][1] = t[1];
                bf[2 * nb + 1][0] = t[2]; bf[2 * nb + 1][1] = t[3];
            }
#pragma unroll
            for (int mi = 0; mi < 2; mi++)
#pragma unroll
                for (int ni = 0; ni < 8; ni++)
                    mma16816(acc[mi][ni], af[mi], bf[ni]);
        }
    }

    // Epilogue: bias add, fp32 stores
    const int row_base = bm * BM + wm * 32 + (lane >> 2);
    const int col_base = bn * BN + wn * 64 + (lane & 3) * 2;
#pragma unroll
    for (int mi = 0; mi < 2; mi++) {
        int row = row_base + mi * 16;
#pragma unroll
        for (int ni = 0; ni < 8; ni++) {
            int col = col_base + ni * 8;
            float2 bv = *reinterpret_cast<const float2*>(bias + col);
            float2 o0 = make_float2(acc[mi][ni][0] + bv.x, acc[mi][ni][1] + bv.y);
            float2 o1 = make_float2(acc[mi][ni][2] + bv.x, acc[mi][ni][3] + bv.y);
            *reinterpret_cast<float2*>(out + (size_t)row * N_ + col) = o0;
            *reinterpret_cast<float2*>(out + (size_t)(row + 8) * N_ + col) = o1;
        }
    }
}

// ---------------------------------------------------------------------------
extern "C" void kernel_launch(void* const* d_in, const int* in_sizes, int n_in,
                              void* d_out, int out_size) {
    const float* x    = (const float*)d_in[0];
    const int*   qw   = (const int*)d_in[1];
    const int*   qz   = (const int*)d_in[2];
    const float* sc   = (const float*)d_in[3];
    const float* bias = (const float*)d_in[4];
    float* out = (float*)d_out;

    // 1) x -> fp16
    round_x_kernel<<<(M_ * (size_t)K_) / 8 / 256, 256>>>(x);
    // 2) dequantize weights -> fp16 g_W[K][N]
    dequant_kernel<<<dim3(NW_ / 256, K_), 256>>>(qw, qz, sc);
    // 3) fp16 tensor-core GEMM + bias
    cudaFuncSetAttribute(gemm_f16_kernel,
                         cudaFuncAttributeMaxDynamicSharedMemorySize, SMEM_TOTAL);
    gemm_f16_kernel<<<(M_ / BM) * (N_ / BN), THREADS, SMEM_TOTAL>>>(bias, out);
}